// round 10
// baseline (speedup 1.0000x reference)
#include <cuda_runtime.h>
#include <cub/cub.cuh>
#include <stdint.h>

#define NMAX 1000000
#define EMAX 8000000
#define SENT 0xFFFFFFFFFFULL  // > any packed edge key ((s<<20)|d with s,d < 2^20)

// node-phase sort buffers (voxel key u32, node id u32)
__device__ unsigned g_vk[NMAX], g_vk2[NMAX];
__device__ unsigned g_vv[NMAX], g_vv2[NMAX];
__device__ int g_inv[NMAX];                    // node -> coarse rank
__device__ unsigned g_seg[NMAX];               // rank -> segment start in sorted order
__device__ unsigned g_flag[EMAX];              // head flags: node phase [0,n), edge phase [0,E)
__device__ unsigned g_pref[EMAX];              // inclusive prefix sums
__device__ unsigned long long g_keys[EMAX], g_keys2[EMAX];
__device__ unsigned g_U;                       // number of unique voxels
// 64 MB CUB temp — VALIDATED: 8 MB crashed the container (onesweep lookback
// overflow past the symbol); 64 MB runs clean.
__device__ __align__(256) unsigned char g_temp[64u << 20];

__global__ void k_vox(const float* __restrict__ pos, const int* __restrict__ batch, int n) {
    int i = blockIdx.x * blockDim.x + threadIdx.x;
    if (i >= n) return;
    float px = pos[3 * i + 0];
    float py = pos[3 * i + 1];
    float pt = pos[3 * i + 2];
    // VALIDATED (R9): match XLA's pos / POOL lowering = multiply by rounded
    // reciprocal, single RN multiply. IEEE division does NOT match.
    int qx = (int)floorf(__fmul_rn(px, 0.25f));
    int qy = (int)floorf(__fmul_rn(py, 0.25f));
    int qt = (int)floorf(__fmul_rn(pt, 0.00025f));
    int b = batch[i];
    g_vk[i] = (unsigned)(((b * 128 + qx) * 128 + qy) * 64 + qt);  // < 2^24
    g_vv[i] = (unsigned)i;
}

__global__ void k_head(const unsigned* __restrict__ sk, int n) {
    int p = blockIdx.x * blockDim.x + threadIdx.x;
    if (p >= n) return;
    unsigned k = sk[p];
    g_flag[p] = (p == 0) || (sk[p - 1] != k);
}

// after InclusiveSum of g_flag -> g_pref: rank of segment containing p = g_pref[p]-1
__global__ void k_nodeinfo(const unsigned* __restrict__ sk, const unsigned* __restrict__ sv,
                           float* __restrict__ out_q, float* __restrict__ out_b,
                           float* __restrict__ out_e, int E, int n) {
    int p = blockIdx.x * blockDim.x + threadIdx.x;
    if (p >= n) return;
    int r = (int)g_pref[p] - 1;
    g_inv[sv[p]] = r;
    if (p == n - 1) g_U = g_pref[p];
    if (!g_flag[p]) return;
    g_seg[r] = (unsigned)p;
    unsigned v = sk[p];
    out_q[3 * r + 0] = (float)((v >> 13) & 127);  // qx
    out_q[3 * r + 1] = (float)((v >> 6) & 127);   // qy
    out_q[3 * r + 2] = (float)(v & 63);           // qt
    out_b[r] = (float)(v >> 20);                  // batch
    out_e[2 * (E + r) + 0] = (float)r;            // self loop
    out_e[2 * (E + r) + 1] = (float)r;
}

// one block (F threads) per output row: direct segmented max, no atomics/enc/dec.
__global__ void k_segmax(const float* __restrict__ x, const unsigned* __restrict__ sv,
                         float* __restrict__ out, int n, int F) {
    int r = blockIdx.x;
    int f = threadIdx.x;
    unsigned U = g_U;
    if ((unsigned)r >= U) {                 // padding row -> zeros
        out[(long long)r * F + f] = 0.0f;
        return;
    }
    int start = (int)g_seg[r];
    int end = ((unsigned)(r + 1) < U) ? (int)g_seg[r + 1] : n;
    float m = -__int_as_float(0x7f800000);  // -inf
    for (int p = start; p < end; p++) {
        m = fmaxf(m, x[(long long)sv[p] * F + f]);
    }
    out[(long long)r * F + f] = m;
}

__global__ void k_fill_neg4(float4* __restrict__ p, int cnt4) {
    int i = blockIdx.x * blockDim.x + threadIdx.x;
    if (i < cnt4) p[i] = make_float4(-1.0f, -1.0f, -1.0f, -1.0f);
}

__global__ void k_ekey(const int2* __restrict__ eidx, int E) {
    int e = blockIdx.x * blockDim.x + threadIdx.x;
    if (e >= E) return;
    int2 sd = eidx[e];
    int s = g_inv[sd.x];
    int d = g_inv[sd.y];
    // (s<<20)|d is order-isomorphic to s*N+d since d < N <= 2^20
    g_keys[e] = (s != d) ? ((((unsigned long long)s) << 20) | (unsigned)d) : SENT;
}

__global__ void k_eflag(const unsigned long long* __restrict__ sk, int E) {
    int e = blockIdx.x * blockDim.x + threadIdx.x;
    if (e >= E) return;
    unsigned long long k = sk[e];
    g_flag[e] = (k != SENT) && (e == 0 || sk[e - 1] != k);
}

__global__ void k_escatter(const unsigned long long* __restrict__ sk,
                           float* __restrict__ out_e, int E) {
    int e = blockIdx.x * blockDim.x + threadIdx.x;
    if (e >= E) return;
    if (!g_flag[e]) return;
    int r = (int)g_pref[e] - 1;             // inclusive scan -> rank
    unsigned long long k = sk[e];
    ((float2*)out_e)[r] = make_float2((float)(unsigned)(k >> 20),
                                      (float)(unsigned)(k & 0xFFFFFu));
}

extern "C" void kernel_launch(void* const* d_in, const int* in_sizes, int n_in,
                              void* d_out, int out_size) {
    const float* x = (const float*)d_in[0];
    const float* pos = (const float*)d_in[1];
    const int* eidx = (const int*)d_in[2];
    const int* batch = (const int*)d_in[3];

    int n = in_sizes[1] / 3;          // nodes
    int F = in_sizes[0] / n;          // feature dim (64)
    int E = in_sizes[2] / 2;          // edges
    float* out = (float*)d_out;

    long long OFF_Q = (long long)n * F;             // uniq_qpos
    long long OFF_E = OFF_Q + 3LL * n;              // ei_out
    long long OFF_B = OFF_E + 2LL * (E + n);        // new_batch

    void *p_vk, *p_vk2, *p_vv, *p_vv2, *p_flag, *p_pref, *p_keys, *p_keys2, *p_temp;
    cudaGetSymbolAddress(&p_vk, g_vk);
    cudaGetSymbolAddress(&p_vk2, g_vk2);
    cudaGetSymbolAddress(&p_vv, g_vv);
    cudaGetSymbolAddress(&p_vv2, g_vv2);
    cudaGetSymbolAddress(&p_flag, g_flag);
    cudaGetSymbolAddress(&p_pref, g_pref);
    cudaGetSymbolAddress(&p_keys, g_keys);
    cudaGetSymbolAddress(&p_keys2, g_keys2);
    cudaGetSymbolAddress(&p_temp, g_temp);

    cudaStream_t s = 0;
    const int T = 256;

    // --- init: qpos + edges + batch regions -> -1 (pooled region fully written later)
    {
        int cnt4 = (int)((out_size - OFF_Q) / 4);   // 22M elems, divisible by 4
        k_fill_neg4<<<(cnt4 + T - 1) / T, T, 0, s>>>((float4*)(out + OFF_Q), cnt4);
    }

    // --- node path: sort 1M (vox,node) pairs on 24-bit key ---
    k_vox<<<(n + T - 1) / T, T, 0, s>>>(pos, batch, n);
    const unsigned *sortedK, *sortedV;
    {
        cub::DoubleBuffer<unsigned> dk((unsigned*)p_vk, (unsigned*)p_vk2);
        cub::DoubleBuffer<unsigned> dv((unsigned*)p_vv, (unsigned*)p_vv2);
        size_t tb = 0;
        cub::DeviceRadixSort::SortPairs(nullptr, tb, dk, dv, n, 0, 24, s);
        cub::DeviceRadixSort::SortPairs(p_temp, tb, dk, dv, n, 0, 24, s);
        sortedK = dk.Current();
        sortedV = dv.Current();
    }
    k_head<<<(n + T - 1) / T, T, 0, s>>>(sortedK, n);
    {
        size_t tb = 0;
        cub::DeviceScan::InclusiveSum(nullptr, tb, (unsigned*)p_flag, (unsigned*)p_pref, n, s);
        cub::DeviceScan::InclusiveSum(p_temp, tb, (unsigned*)p_flag, (unsigned*)p_pref, n, s);
    }
    k_nodeinfo<<<(n + T - 1) / T, T, 0, s>>>(sortedK, sortedV,
                                             out + OFF_Q, out + OFF_B, out + OFF_E, E, n);

    // --- pooled features: direct segmented max (no atomics, no init pass) ---
    k_segmax<<<n, F, 0, s>>>(x, sortedV, out, n, F);

    // --- edge path: remap -> 40-bit radix sort -> unique -> scatter ---
    k_ekey<<<(E + T - 1) / T, T, 0, s>>>((const int2*)eidx, E);
    const unsigned long long* sorted;
    {
        cub::DoubleBuffer<unsigned long long> dk((unsigned long long*)p_keys,
                                                 (unsigned long long*)p_keys2);
        size_t tb = 0;
        cub::DeviceRadixSort::SortKeys(nullptr, tb, dk, E, 0, 40, s);
        cub::DeviceRadixSort::SortKeys(p_temp, tb, dk, E, 0, 40, s);
        sorted = dk.Current();
    }
    k_eflag<<<(E + T - 1) / T, T, 0, s>>>(sorted, E);
    {
        size_t tb = 0;
        cub::DeviceScan::InclusiveSum(nullptr, tb, (unsigned*)p_flag, (unsigned*)p_pref, E, s);
        cub::DeviceScan::InclusiveSum(p_temp, tb, (unsigned*)p_flag, (unsigned*)p_pref, E, s);
    }
    k_escatter<<<(E + T - 1) / T, T, 0, s>>>(sorted, out + OFF_E, E);
}

// round 11
// speedup vs baseline: 1.3110x; 1.3110x over previous
#include <cuda_runtime.h>
#include <cub/cub.cuh>
#include <thrust/iterator/counting_iterator.h>
#include <thrust/iterator/transform_iterator.h>
#include <stdint.h>

#define NMAX 1000000
#define EMAX 8000000
#define SENT 0xFFFFFFFFFFULL  // > any packed edge key ((s<<20)|d with s,d < 2^20)

// node-phase sort buffers (voxel key u32, node id u32)
__device__ unsigned g_vk[NMAX], g_vk2[NMAX];
__device__ unsigned g_vv[NMAX], g_vv2[NMAX];
__device__ int g_inv[NMAX];                    // node -> coarse rank
__device__ unsigned g_seg[NMAX];               // rank -> segment start in sorted order
__device__ unsigned g_pref[EMAX];              // inclusive prefix sums (node phase reuses low 1M)
__device__ unsigned long long g_keys[EMAX], g_keys2[EMAX];
__device__ unsigned g_U;                       // number of unique voxels
// 64 MB CUB temp — VALIDATED: 8 MB crashed the container (onesweep lookback
// overflow past the symbol); 64 MB runs clean.
__device__ __align__(256) unsigned char g_temp[64u << 20];

__global__ void k_vox(const float* __restrict__ pos, const int* __restrict__ batch, int n) {
    int i = blockIdx.x * blockDim.x + threadIdx.x;
    if (i >= n) return;
    float px = pos[3 * i + 0];
    float py = pos[3 * i + 1];
    float pt = pos[3 * i + 2];
    // VALIDATED (R9): match XLA's pos / POOL lowering = multiply by rounded
    // reciprocal, single RN multiply. IEEE division does NOT match.
    int qx = (int)floorf(__fmul_rn(px, 0.25f));
    int qy = (int)floorf(__fmul_rn(py, 0.25f));
    int qt = (int)floorf(__fmul_rn(pt, 0.00025f));
    int b = batch[i];
    g_vk[i] = (unsigned)(((b * 128 + qx) * 128 + qy) * 64 + qt);  // < 2^24
    g_vv[i] = (unsigned)i;
}

// head-flag-on-the-fly functors for the scans (no materialized flag array)
struct NodeHeadOp {
    const unsigned* sk;
    __host__ __device__ __forceinline__ unsigned operator()(int p) const {
        return (p == 0) || (sk[p] != sk[p - 1]);
    }
};
struct EdgeHeadOp {
    const unsigned long long* sk;
    __host__ __device__ __forceinline__ unsigned operator()(int e) const {
        unsigned long long k = sk[e];
        return (k != SENT) && ((e == 0) || (sk[e - 1] != k));
    }
};

// after InclusiveSum of head flags -> g_pref:
//   head p: rank r = g_pref[p]-1;  non-head p: pad slot = U + (p - g_pref[p])
__global__ void k_nodeinfo(const unsigned* __restrict__ sk, const unsigned* __restrict__ sv,
                           float* __restrict__ out_q, float* __restrict__ out_b,
                           float* __restrict__ out_e, int E, int n) {
    int p = blockIdx.x * blockDim.x + threadIdx.x;
    if (p >= n) return;
    int U = (int)g_pref[n - 1];
    if (p == n - 1) g_U = (unsigned)U;
    unsigned k = sk[p];
    int pr = (int)g_pref[p];
    g_inv[sv[p]] = pr - 1;
    bool head = (p == 0) || (sk[p - 1] != k);
    if (head) {
        int r = pr - 1;
        g_seg[r] = (unsigned)p;
        out_q[3 * r + 0] = (float)((k >> 13) & 127);  // qx
        out_q[3 * r + 1] = (float)((k >> 6) & 127);   // qy
        out_q[3 * r + 2] = (float)(k & 63);           // qt
        out_b[r] = (float)(k >> 20);                  // batch
        ((float2*)out_e)[E + r] = make_float2((float)r, (float)r);  // self loop
    } else {
        int pad = U + (p - pr);        // distinct slots in [U, n)
        out_q[3 * pad + 0] = -1.0f;
        out_q[3 * pad + 1] = -1.0f;
        out_q[3 * pad + 2] = -1.0f;
        out_b[pad] = -1.0f;
        ((float2*)out_e)[E + pad] = make_float2(-1.0f, -1.0f);
    }
}

// grid-stride segmented max: fixed grid -> single wave, no wave-transition cost.
// 256 threads = 4 row-groups of 64 (F) threads.
__global__ void k_segmax(const float* __restrict__ x, const unsigned* __restrict__ sv,
                         float* __restrict__ out, int n, int F) {
    int U = (int)g_U;
    int rpb = blockDim.x / F;                       // rows per block iteration
    int f = threadIdx.x % F;
    int r0 = blockIdx.x * rpb + threadIdx.x / F;
    int rstride = gridDim.x * rpb;
    for (int r = r0; r < n; r += rstride) {
        if (r >= U) {
            out[(long long)r * F + f] = 0.0f;       // padding row
            continue;
        }
        int start = (int)g_seg[r];
        int end = (r + 1 < U) ? (int)g_seg[r + 1] : n;
        float m = -__int_as_float(0x7f800000);      // -inf
        for (int p = start; p < end; p++)
            m = fmaxf(m, x[(long long)sv[p] * F + f]);
        out[(long long)r * F + f] = m;
    }
}

__global__ void k_ekey(const int2* __restrict__ eidx, int E) {
    int e = blockIdx.x * blockDim.x + threadIdx.x;
    if (e >= E) return;
    int2 sd = eidx[e];
    int s = g_inv[sd.x];
    int d = g_inv[sd.y];
    // (s<<20)|d is order-isomorphic to s*N+d since d < N <= 2^20
    g_keys[e] = (s != d) ? ((((unsigned long long)s) << 20) | (unsigned)d) : SENT;
}

// heads write their unique edge at rank; non-heads write the -1 pad row.
__global__ void k_escatter(const unsigned long long* __restrict__ sk,
                           float2* __restrict__ out_e, int E) {
    int e = blockIdx.x * blockDim.x + threadIdx.x;
    if (e >= E) return;
    int M = (int)g_pref[E - 1];
    unsigned long long k = sk[e];
    int pr = (int)g_pref[e];
    bool head = (k != SENT) && ((e == 0) || (sk[e - 1] != k));
    if (head) {
        out_e[pr - 1] = make_float2((float)(unsigned)(k >> 20),
                                    (float)(unsigned)(k & 0xFFFFFu));
    } else {
        out_e[M + (e - pr)] = make_float2(-1.0f, -1.0f);  // distinct slots in [M, E)
    }
}

extern "C" void kernel_launch(void* const* d_in, const int* in_sizes, int n_in,
                              void* d_out, int out_size) {
    const float* x = (const float*)d_in[0];
    const float* pos = (const float*)d_in[1];
    const int* eidx = (const int*)d_in[2];
    const int* batch = (const int*)d_in[3];

    int n = in_sizes[1] / 3;          // nodes
    int F = in_sizes[0] / n;          // feature dim (64)
    int E = in_sizes[2] / 2;          // edges
    float* out = (float*)d_out;

    long long OFF_Q = (long long)n * F;             // uniq_qpos
    long long OFF_E = OFF_Q + 3LL * n;              // ei_out
    long long OFF_B = OFF_E + 2LL * (E + n);        // new_batch

    void *p_vk, *p_vk2, *p_vv, *p_vv2, *p_pref, *p_keys, *p_keys2, *p_temp;
    cudaGetSymbolAddress(&p_vk, g_vk);
    cudaGetSymbolAddress(&p_vk2, g_vk2);
    cudaGetSymbolAddress(&p_vv, g_vv);
    cudaGetSymbolAddress(&p_vv2, g_vv2);
    cudaGetSymbolAddress(&p_pref, g_pref);
    cudaGetSymbolAddress(&p_keys, g_keys);
    cudaGetSymbolAddress(&p_keys2, g_keys2);
    cudaGetSymbolAddress(&p_temp, g_temp);

    cudaStream_t s = 0;
    const int T = 256;

    // --- node path: sort 1M (vox,node) pairs on 24-bit key ---
    k_vox<<<(n + T - 1) / T, T, 0, s>>>(pos, batch, n);
    const unsigned *sortedK, *sortedV;
    {
        cub::DoubleBuffer<unsigned> dk((unsigned*)p_vk, (unsigned*)p_vk2);
        cub::DoubleBuffer<unsigned> dv((unsigned*)p_vv, (unsigned*)p_vv2);
        size_t tb = 0;
        cub::DeviceRadixSort::SortPairs(nullptr, tb, dk, dv, n, 0, 24, s);
        cub::DeviceRadixSort::SortPairs(p_temp, tb, dk, dv, n, 0, 24, s);
        sortedK = dk.Current();
        sortedV = dv.Current();
    }
    {   // inclusive scan of on-the-fly head flags
        NodeHeadOp op{sortedK};
        auto it = thrust::make_transform_iterator(thrust::make_counting_iterator(0), op);
        size_t tb = 0;
        cub::DeviceScan::InclusiveSum(nullptr, tb, it, (unsigned*)p_pref, n, s);
        cub::DeviceScan::InclusiveSum(p_temp, tb, it, (unsigned*)p_pref, n, s);
    }
    k_nodeinfo<<<(n + T - 1) / T, T, 0, s>>>(sortedK, sortedV,
                                             out + OFF_Q, out + OFF_B, out + OFF_E, E, n);

    // --- pooled features: grid-stride segmented max ---
    k_segmax<<<2048, T, 0, s>>>(x, sortedV, out, n, F);

    // --- edge path: remap -> 40-bit radix sort -> scan -> scatter (+pads) ---
    k_ekey<<<(E + T - 1) / T, T, 0, s>>>((const int2*)eidx, E);
    const unsigned long long* sorted;
    {
        cub::DoubleBuffer<unsigned long long> dk((unsigned long long*)p_keys,
                                                 (unsigned long long*)p_keys2);
        size_t tb = 0;
        cub::DeviceRadixSort::SortKeys(nullptr, tb, dk, E, 0, 40, s);
        cub::DeviceRadixSort::SortKeys(p_temp, tb, dk, E, 0, 40, s);
        sorted = dk.Current();
    }
    {   // inclusive scan of on-the-fly edge head flags
        EdgeHeadOp op{sorted};
        auto it = thrust::make_transform_iterator(thrust::make_counting_iterator(0), op);
        size_t tb = 0;
        cub::DeviceScan::InclusiveSum(nullptr, tb, it, (unsigned*)p_pref, E, s);
        cub::DeviceScan::InclusiveSum(p_temp, tb, it, (unsigned*)p_pref, E, s);
    }
    k_escatter<<<(E + T - 1) / T, T, 0, s>>>(sorted, (float2*)(out + OFF_E), E);
}